// round 7
// baseline (speedup 1.0000x reference)
#include <cuda_runtime.h>
#include <math.h>

#define NN 25000
#define NE 400000
#define ND 100
#define EDICT 16

// ---------------- device scratch (zero-initialized at module load; k3 restores) ----------------
__device__ float4   g_tabT[ND * 32];        // P table: [d][f] -> 4 heads (51.2KB)
__device__ float4   g_s1[ND];
__device__ float4   g_s2[ND];
__device__ float4   g_s3[EDICT];
__device__ float4   g_lnedge[EDICT * 32];   // 16 LN'd edge rows (8KB)
__device__ int      g_deg[NN];
__device__ unsigned g_mask[NN * 4];         // per-node 100-bit dict-slot mask (400KB)
__device__ float4   g_Wmat[NN * ND];        // [t][d] -> per-head sum of exp (40MB)

// ==================== K1: dict tables only (K-split GEMV) ====================
#define TAB_BLKS (ND + EDICT)     // 116

__global__ void __launch_bounds__(256) k1_tables(
    const float* __restrict__ node_emb, const float* __restrict__ edge_emb,
    const float* __restrict__ W_t, const float* __restrict__ b_t,
    const float* __restrict__ W_e, const float* __restrict__ b_e,
    const float* __restrict__ a_w,
    const float* __restrict__ gamma, const float* __restrict__ beta)
{
    __shared__ float sh[128];
    __shared__ float part[128];
    __shared__ float red[8];
    int b = blockIdx.x;
    int tid = threadIdx.x;
    int col = tid & 127;
    int half = tid >> 7;
    bool isnode = (b < ND);
    const float* emb  = isnode ? (node_emb + b * 128) : (edge_emb + (b - ND) * 128);
    const float* W    = isnode ? W_t : W_e;
    const float* bias = isnode ? b_t : b_e;

    if (half == 0) sh[col] = emb[col];
    __syncthreads();

    int k0 = half * 64;
    float a0 = 0.f, a1 = 0.f;
#pragma unroll
    for (int i = 0; i < 64; i += 2) {
        a0 += sh[k0 + i]     * W[(k0 + i) * 128 + col];
        a1 += sh[k0 + i + 1] * W[(k0 + i + 1) * 128 + col];
    }
    float partial = a0 + a1;
    if (half == 1) part[col] = partial;
    __syncthreads();
    if (half == 1) return;

    float acc = partial + part[col] + bias[col];

    int h = col >> 5;
    int f = col & 31;

    if (isnode) {
        ((float*)&g_tabT[b * 32 + f])[h] = acc;
        float u = acc * a_w[f];
        float v = acc * a_w[32 + f];
#pragma unroll
        for (int o = 16; o; o >>= 1) {
            u += __shfl_xor_sync(0xFFFFFFFFu, u, o);
            v += __shfl_xor_sync(0xFFFFFFFFu, v, o);
        }
        if (f == 0) {
            ((float*)&g_s1[b])[h] = u;
            ((float*)&g_s2[b])[h] = v;
        }
    } else {
        int k = b - ND;
        float u = acc * a_w[64 + f];
        float s = acc;
#pragma unroll
        for (int o = 16; o; o >>= 1) {
            u += __shfl_xor_sync(0xFFFFFFFFu, u, o);
            s += __shfl_xor_sync(0xFFFFFFFFu, s, o);
        }
        if (f == 0) {
            ((float*)&g_s3[k])[h] = u;
            red[h] = s;
        }
        __syncthreads();
        float mu = (red[0] + red[1] + red[2] + red[3]) * (1.f / 128.f);
        float dd = acc - mu;
        float sq = dd * dd;
#pragma unroll
        for (int o = 16; o; o >>= 1) sq += __shfl_xor_sync(0xFFFFFFFFu, sq, o);
        if (f == 0) red[4 + h] = sq;
        __syncthreads();
        float var = (red[4] + red[5] + red[6] + red[7]) * (1.f / 128.f);
        float val = dd * rsqrtf(var + 1e-5f) * gamma[col] + beta[col];
        ((float*)g_lnedge)[k * 128 + col] = val;
    }
}

// ---------------- unrolled edge-out streamer (4-way MLP) ----------------
__device__ __forceinline__ void eout_stream(const int* __restrict__ ef,
                                            float4* __restrict__ out_edge,
                                            int start, int end, int gw, int l, int stride)
{
    int e = start + gw;
    for (; e + 3 * stride < end; e += 4 * stride) {
        int k0 = __ldg(&ef[e]);
        int k1 = __ldg(&ef[e + stride]);
        int k2 = __ldg(&ef[e + 2 * stride]);
        int k3 = __ldg(&ef[e + 3 * stride]);
        float4 v0 = g_lnedge[(k0 << 5) + l];
        float4 v1 = g_lnedge[(k1 << 5) + l];
        float4 v2 = g_lnedge[(k2 << 5) + l];
        float4 v3 = g_lnedge[(k3 << 5) + l];
        __stcs(&out_edge[(size_t)e * 32 + l], v0);
        __stcs(&out_edge[(size_t)(e + stride) * 32 + l], v1);
        __stcs(&out_edge[(size_t)(e + 2 * stride) * 32 + l], v2);
        __stcs(&out_edge[(size_t)(e + 3 * stride) * 32 + l], v3);
    }
    for (; e < end; e += stride) {
        int k = __ldg(&ef[e]);
        __stcs(&out_edge[(size_t)e * 32 + l], g_lnedge[(k << 5) + l]);
    }
}

// ==================== K2: edge atomics (1/4 of blocks) + edge-out A (3/4) ====================
#define CMP_BLKS 300
#define EO_BLKS  900
#define K_TOT    1200               // mod-4 interleave: m==0 -> compute
#define EO_SPLIT (NE / 2)           // 200000

__global__ void __launch_bounds__(256) k2_edges(
    const int* __restrict__ nf, const int* __restrict__ ef,
    const int* __restrict__ ei, const float* __restrict__ a_b,
    float4* __restrict__ out_edge)
{
    int bid = blockIdx.x;
    int tid = threadIdx.x;
    int m = bid & 3;

    if (m != 0) {
        // ---- edge-out streaming: edges [0, EO_SPLIT) ----
        int eb = bid - bid / 4 - 1;          // 0..EO_BLKS-1
        int l = tid & 31;
        int gw = eb * 8 + (tid >> 5);
        eout_stream(ef, out_edge, 0, EO_SPLIT, gw, l, EO_BLKS * 8);
        return;
    }

    // ---- edge logit pass, grid-strided ----
    int cb = bid >> 2;                       // 0..CMP_BLKS-1
    float ab = __ldg(a_b);
    for (int e = cb * 256 + tid; e < NE; e += CMP_BLKS * 256) {
        int s = __ldg(&ei[e]);
        int t = __ldg(&ei[NE + e]);
        int k = __ldg(&ef[e]);
        int ds = __ldg(&nf[s]);
        int dt = __ldg(&nf[t]);
        float4 z1 = g_s1[dt];
        float4 z2 = g_s2[ds];
        float4 z3 = g_s3[k];

        float zx = z1.x + z2.x + z3.x + ab;
        float zy = z1.y + z2.y + z3.y + ab;
        float zz = z1.z + z2.z + z3.z + ab;
        float zw = z1.w + z2.w + z3.w + ab;
        zx = zx >= 0.f ? zx : 0.2f * zx;
        zy = zy >= 0.f ? zy : 0.2f * zy;
        zz = zz >= 0.f ? zz : 0.2f * zz;
        zw = zw >= 0.f ? zw : 0.2f * zw;
        float ex = __expf(zx), ey = __expf(zy), ez = __expf(zz), ew = __expf(zw);

        float4* wp = &g_Wmat[t * ND + ds];
        asm volatile("red.global.add.v4.f32 [%0], {%1,%2,%3,%4};"
                     :: "l"(wp), "f"(ex), "f"(ey), "f"(ez), "f"(ew) : "memory");
        atomicOr(&g_mask[(t << 2) + (ds >> 5)], 1u << (ds & 31));
        atomicAdd(&g_deg[t], 1);
    }
}

// ==================== K3: sparse node recombine+LN (1/4) + edge-out B (3/4) ====================
__global__ void __launch_bounds__(256) k3_nodes(
    const int* __restrict__ nf, const int* __restrict__ ef,
    const float* __restrict__ gamma, const float* __restrict__ beta,
    float* __restrict__ out_node, float4* __restrict__ out_edge)
{
    int bid = blockIdx.x;
    int tid = threadIdx.x;
    int m = bid & 3;
    int l = tid & 31;

    if (m != 0) {
        // ---- edge-out streaming: edges [EO_SPLIT, NE) ----
        int eb = bid - bid / 4 - 1;
        int gw = eb * 8 + (tid >> 5);
        eout_stream(ef, out_edge, EO_SPLIT, NE, gw, l, EO_BLKS * 8);
        return;
    }

    // ---- node pass: each warp handles node pairs, grid-strided ----
    int cb = bid >> 2;
    int warp0 = cb * 8 + (tid >> 5);
    const float4 z4 = make_float4(0.f, 0.f, 0.f, 0.f);

    float gl0 = gamma[l],      bl0 = beta[l];
    float gl1 = gamma[32 + l], bl1 = beta[32 + l];
    float gl2 = gamma[64 + l], bl2 = beta[64 + l];
    float gl3 = gamma[96 + l], bl3 = beta[96 + l];

    for (int task = warp0; task < NN / 2; task += CMP_BLKS * 8) {
        int n0 = 2 * task;
        int n1 = 2 * task + 1;

        unsigned um[4];
#pragma unroll
        for (int w = 0; w < 4; w++)
            um[w] = __ldg(&g_mask[(n0 << 2) + w]) | __ldg(&g_mask[(n1 << 2) + w]);

        float4 acc0 = z4, acc1 = z4, ss0 = z4, ss1 = z4;

#pragma unroll
        for (int w = 0; w < 4; w++) {
            unsigned bits = um[w];
            while (bits) {
                int d = (w << 5) + __ffs(bits) - 1;
                bits &= bits - 1;
                float4 w0 = __ldcs(&g_Wmat[n0 * ND + d]);   // 0 if only n1 touched
                float4 w1 = __ldcs(&g_Wmat[n1 * ND + d]);
                float4 p  = __ldg(&g_tabT[(d << 5) + l]);
                acc0.x += w0.x * p.x; acc0.y += w0.y * p.y; acc0.z += w0.z * p.z; acc0.w += w0.w * p.w;
                acc1.x += w1.x * p.x; acc1.y += w1.y * p.y; acc1.z += w1.z * p.z; acc1.w += w1.w * p.w;
                ss0.x += w0.x; ss0.y += w0.y; ss0.z += w0.z; ss0.w += w0.w;
                ss1.x += w1.x; ss1.y += w1.y; ss1.z += w1.z; ss1.w += w1.w;
                if (l == 0) {                                // restore zeros for next replay
                    g_Wmat[n0 * ND + d] = z4;
                    g_Wmat[n1 * ND + d] = z4;
                }
            }
        }

        int dg0 = __ldg(&g_deg[n0]);
        int dg1 = __ldg(&g_deg[n1]);
        // restore masks + deg
        if (l < 4) {
            g_mask[(n0 << 2) + l] = 0u;
            g_mask[(n1 << 2) + l] = 0u;
        }
        if (l == 0) { g_deg[n0] = 0; g_deg[n1] = 0; }

#pragma unroll
        for (int n = 0; n < 2; n++) {
            int t = n == 0 ? n0 : n1;
            float4 a  = n == 0 ? acc0 : acc1;
            float4 ss = n == 0 ? ss0  : ss1;
            float dg  = (float)(n == 0 ? dg0 : dg1);
            float r0 = ss.x > 0.f ? 1.f / ss.x : 0.f;
            float r1 = ss.y > 0.f ? 1.f / ss.y : 0.f;
            float r2 = ss.z > 0.f ? 1.f / ss.z : 0.f;
            float r3 = ss.w > 0.f ? 1.f / ss.w : 0.f;
            float4 p = __ldg(&g_tabT[(__ldg(&nf[t]) << 5) + l]);

            float v0 = a.x * r0 + dg * p.x;
            float v1 = a.y * r1 + dg * p.y;
            float v2 = a.z * r2 + dg * p.z;
            float v3 = a.w * r3 + dg * p.w;

            float s = v0 + v1 + v2 + v3;
#pragma unroll
            for (int o = 16; o; o >>= 1) s += __shfl_xor_sync(0xFFFFFFFFu, s, o);
            float mu = s * (1.f / 128.f);
            float d0 = v0 - mu, d1 = v1 - mu, d2 = v2 - mu, d3 = v3 - mu;
            float sq = d0 * d0 + d1 * d1 + d2 * d2 + d3 * d3;
#pragma unroll
            for (int o = 16; o; o >>= 1) sq += __shfl_xor_sync(0xFFFFFFFFu, sq, o);
            float rs = rsqrtf(sq * (1.f / 128.f) + 1e-5f);

            float* o0 = out_node + (size_t)t * 128;
            __stcs(&o0[l],      d0 * rs * gl0 + bl0);
            __stcs(&o0[32 + l], d1 * rs * gl1 + bl1);
            __stcs(&o0[64 + l], d2 * rs * gl2 + bl2);
            __stcs(&o0[96 + l], d3 * rs * gl3 + bl3);
        }
    }
}

// ==================== launch ====================
extern "C" void kernel_launch(void* const* d_in, const int* in_sizes, int n_in,
                              void* d_out, int out_size) {
    const int*   nf       = (const int*)d_in[0];
    const int*   ef       = (const int*)d_in[1];
    const int*   ei       = (const int*)d_in[2];
    const float* node_emb = (const float*)d_in[3];
    const float* edge_emb = (const float*)d_in[4];
    const float* W_t      = (const float*)d_in[5];
    const float* b_t      = (const float*)d_in[6];
    const float* W_e      = (const float*)d_in[7];
    const float* b_e      = (const float*)d_in[8];
    const float* a_w      = (const float*)d_in[9];
    const float* a_b      = (const float*)d_in[10];
    const float* gamma    = (const float*)d_in[11];
    const float* beta     = (const float*)d_in[12];

    float* out_node = (float*)d_out;                                  // [25000,128]
    float4* out_edge = (float4*)((float*)d_out + (size_t)NN * 128);   // [400000,128]

    k1_tables<<<TAB_BLKS, 256>>>(node_emb, edge_emb, W_t, b_t, W_e, b_e,
                                 a_w, gamma, beta);
    k2_edges<<<K_TOT, 256>>>(nf, ef, ei, a_b, out_edge);
    k3_nodes<<<K_TOT, 256>>>(nf, ef, gamma, beta, out_node, out_edge);
}

// round 8
// speedup vs baseline: 1.3519x; 1.3519x over previous
#include <cuda_runtime.h>
#include <math.h>

#define NN 25000
#define NE 400000
#define ND 100
#define EDICT 16

// ---------------- device scratch ----------------
__device__ float4 g_tabT[ND * 32];        // P table: [d][f] -> 4 heads (51.2KB)
__device__ float4 g_s1[ND];
__device__ float4 g_s2[ND];
__device__ float4 g_s3[EDICT];
__device__ float4 g_lnedge[EDICT * 32];   // 16 LN'd edge rows (8KB)
__device__ int    g_deg[NN];
__device__ float4 g_Wmat[NN * ND];        // [t][d] -> per-head sum of exp (40MB)
__device__ int    g_ctrA;                 // eout chunk counter for k2
__device__ int    g_ctrB;                 // eout chunk counter for k3

// ---------------- eout chunking ----------------
#define CHUNK_E 384
#define N_CHUNKS ((NE + CHUNK_E - 1) / CHUNK_E)   // 1042
#define CHUNK_SPLIT (N_CHUNKS / 2)                // 521: k2 handles [0,521), k3 [521,1042)

// ==================== K1: fused tables (4-chain K-split) + zero + ctr reset ====================
#define TAB_BLKS (ND + EDICT)     // 116
#define ZBLK 2048
#define K1_TOT (TAB_BLKS + ZBLK)

__global__ void __launch_bounds__(256) k1_init(
    const float* __restrict__ node_emb, const float* __restrict__ edge_emb,
    const float* __restrict__ W_t, const float* __restrict__ b_t,
    const float* __restrict__ W_e, const float* __restrict__ b_e,
    const float* __restrict__ a_w,
    const float* __restrict__ gamma, const float* __restrict__ beta)
{
    int b = blockIdx.x;
    int tid = threadIdx.x;

    if (b == 0 && tid == 0) { g_ctrA = 0; g_ctrB = 0; }

    if (b >= TAB_BLKS) {
        // ---- zero blocks: grid-stride over Wmat + deg ----
        int idx = (b - TAB_BLKS) * 256 + tid;
        const int stride = ZBLK * 256;
        float4 z = make_float4(0.f, 0.f, 0.f, 0.f);
        for (int i = idx; i < NN * ND; i += stride) g_Wmat[i] = z;
        for (int i = idx; i < NN; i += stride) g_deg[i] = 0;
        return;
    }

    // ---- table block: one dict row, K split in halves, 4 chains each ----
    __shared__ float sh[128];
    __shared__ float part[128];
    __shared__ float red[8];
    int col = tid & 127;
    int half = tid >> 7;
    bool isnode = (b < ND);
    const float* emb  = isnode ? (node_emb + b * 128) : (edge_emb + (b - ND) * 128);
    const float* W    = isnode ? W_t : W_e;
    const float* bias = isnode ? b_t : b_e;

    if (half == 0) sh[col] = emb[col];
    __syncthreads();

    int k0 = half * 64;
    float a0 = 0.f, a1 = 0.f, a2 = 0.f, a3 = 0.f;
#pragma unroll
    for (int i = 0; i < 64; i += 4) {
        a0 += sh[k0 + i]     * W[(k0 + i) * 128 + col];
        a1 += sh[k0 + i + 1] * W[(k0 + i + 1) * 128 + col];
        a2 += sh[k0 + i + 2] * W[(k0 + i + 2) * 128 + col];
        a3 += sh[k0 + i + 3] * W[(k0 + i + 3) * 128 + col];
    }
    float partial = (a0 + a1) + (a2 + a3);
    if (half == 1) part[col] = partial;
    __syncthreads();
    if (half == 1) return;

    float acc = partial + part[col] + bias[col];

    int h = col >> 5;
    int f = col & 31;

    if (isnode) {
        ((float*)&g_tabT[b * 32 + f])[h] = acc;
        float u = acc * a_w[f];
        float v = acc * a_w[32 + f];
#pragma unroll
        for (int o = 16; o; o >>= 1) {
            u += __shfl_xor_sync(0xFFFFFFFFu, u, o);
            v += __shfl_xor_sync(0xFFFFFFFFu, v, o);
        }
        if (f == 0) {
            ((float*)&g_s1[b])[h] = u;
            ((float*)&g_s2[b])[h] = v;
        }
    } else {
        int k = b - ND;
        float u = acc * a_w[64 + f];
        float s = acc;
#pragma unroll
        for (int o = 16; o; o >>= 1) {
            u += __shfl_xor_sync(0xFFFFFFFFu, u, o);
            s += __shfl_xor_sync(0xFFFFFFFFu, s, o);
        }
        if (f == 0) {
            ((float*)&g_s3[k])[h] = u;
            red[h] = s;
        }
        __syncthreads();
        float mu = (red[0] + red[1] + red[2] + red[3]) * (1.f / 128.f);
        float dd = acc - mu;
        float sq = dd * dd;
#pragma unroll
        for (int o = 16; o; o >>= 1) sq += __shfl_xor_sync(0xFFFFFFFFu, sq, o);
        if (f == 0) red[4 + h] = sq;
        __syncthreads();
        float var = (red[4] + red[5] + red[6] + red[7]) * (1.f / 128.f);
        float val = dd * rsqrtf(var + 1e-5f) * gamma[col] + beta[col];
        ((float*)g_lnedge)[k * 128 + col] = val;
    }
}

// ---------------- process one eout chunk (warp-per-edge, 4-way MLP) ----------------
__device__ __forceinline__ void eout_chunk(const int* __restrict__ ef,
                                           float4* __restrict__ out_edge,
                                           int c, int tid)
{
    int w = tid >> 5, l = tid & 31;
    int base = c * CHUNK_E;
    int end = base + CHUNK_E;
    if (end > NE) end = NE;
    int e = base + w;
    for (; e + 24 < end; e += 32) {
        int k0 = __ldg(&ef[e]);
        int k1 = __ldg(&ef[e + 8]);
        int k2 = __ldg(&ef[e + 16]);
        int k3 = __ldg(&ef[e + 24]);
        float4 v0 = g_lnedge[(k0 << 5) + l];
        float4 v1 = g_lnedge[(k1 << 5) + l];
        float4 v2 = g_lnedge[(k2 << 5) + l];
        float4 v3 = g_lnedge[(k3 << 5) + l];
        __stcs(&out_edge[(size_t)e * 32 + l], v0);
        __stcs(&out_edge[(size_t)(e + 8) * 32 + l], v1);
        __stcs(&out_edge[(size_t)(e + 16) * 32 + l], v2);
        __stcs(&out_edge[(size_t)(e + 24) * 32 + l], v3);
    }
    for (; e < end; e += 8) {
        int k = __ldg(&ef[e]);
        __stcs(&out_edge[(size_t)e * 32 + l], g_lnedge[(k << 5) + l]);
    }
}

#define KBLKS 1184
#define NCMP  395     // blocks with bid%3==0 do compute first

// ==================== K2: edge atomics + eout chunks [0, CHUNK_SPLIT) ====================
__global__ void __launch_bounds__(256) k2_edges(
    const int* __restrict__ nf, const int* __restrict__ ef,
    const int* __restrict__ ei, const float* __restrict__ a_b,
    float4* __restrict__ out_edge)
{
    int bid = blockIdx.x;
    int tid = threadIdx.x;
    __shared__ int s_chunk;

    if (bid % 3 == 0) {
        // ---- edge logit pass, grid-strided ----
        int cb = bid / 3;
        float ab = __ldg(a_b);
        for (int e = cb * 256 + tid; e < NE; e += NCMP * 256) {
            int s = __ldg(&ei[e]);
            int t = __ldg(&ei[NE + e]);
            int k = __ldg(&ef[e]);
            int ds = __ldg(&nf[s]);
            int dt = __ldg(&nf[t]);
            float4 z1 = g_s1[dt];
            float4 z2 = g_s2[ds];
            float4 z3 = g_s3[k];

            float zx = z1.x + z2.x + z3.x + ab;
            float zy = z1.y + z2.y + z3.y + ab;
            float zz = z1.z + z2.z + z3.z + ab;
            float zw = z1.w + z2.w + z3.w + ab;
            zx = zx >= 0.f ? zx : 0.2f * zx;
            zy = zy >= 0.f ? zy : 0.2f * zy;
            zz = zz >= 0.f ? zz : 0.2f * zz;
            zw = zw >= 0.f ? zw : 0.2f * zw;
            float ex = __expf(zx), ey = __expf(zy), ez = __expf(zz), ew = __expf(zw);

            float4* wp = &g_Wmat[t * ND + ds];
            asm volatile("red.global.add.v4.f32 [%0], {%1,%2,%3,%4};"
                         :: "l"(wp), "f"(ex), "f"(ey), "f"(ez), "f"(ew) : "memory");
            atomicAdd(&g_deg[t], 1);
        }
    }

    // ---- steal eout chunks [0, CHUNK_SPLIT) ----
    for (;;) {
        if (tid == 0) s_chunk = atomicAdd(&g_ctrA, 1);
        __syncthreads();
        int c = s_chunk;
        __syncthreads();
        if (c >= CHUNK_SPLIT) break;
        eout_chunk(ef, out_edge, c, tid);
    }
}

// ==================== K3: dense node GEMM+LN + eout chunks [CHUNK_SPLIT, N_CHUNKS) ====================
#define NPB3 16
#define NT3 ((NN + NPB3 - 1) / NPB3)   // 1563 node tiles

__global__ void __launch_bounds__(256) k3_nodes(
    const int* __restrict__ nf, const int* __restrict__ ef,
    const float* __restrict__ gamma, const float* __restrict__ beta,
    float* __restrict__ out_node, float4* __restrict__ out_edge)
{
    int bid = blockIdx.x;
    int tid = threadIdx.x;
    __shared__ float4 Ws[NPB3 * ND];   // 25.6KB static
    __shared__ int s_chunk;

    if (bid % 3 == 0) {
        int cb = bid / 3;
        int w = tid >> 5, l = tid & 31;
        float gl0 = gamma[l],      bl0 = beta[l];
        float gl1 = gamma[32 + l], bl1 = beta[32 + l];
        float gl2 = gamma[64 + l], bl2 = beta[64 + l];
        float gl3 = gamma[96 + l], bl3 = beta[96 + l];

        for (int tile = cb; tile < NT3; tile += NCMP) {
            int base = tile * NPB3;
            __syncthreads();   // protect Ws reuse across tiles
            for (int i = tid; i < NPB3 * ND; i += 256) {
                int t = base + i / ND;
                Ws[i] = (t < NN) ? __ldcs(&g_Wmat[t * ND + (i % ND)])
                                 : make_float4(0.f, 0.f, 0.f, 0.f);
            }
            __syncthreads();

            const float4* Wa = &Ws[(2 * w + 0) * ND];
            const float4* Wb = &Ws[(2 * w + 1) * ND];
            float4 acc0 = make_float4(0.f, 0.f, 0.f, 0.f);
            float4 acc1 = make_float4(0.f, 0.f, 0.f, 0.f);
            float4 ss0  = make_float4(0.f, 0.f, 0.f, 0.f);
            float4 ss1  = make_float4(0.f, 0.f, 0.f, 0.f);

#pragma unroll 4
            for (int d = 0; d < ND; d++) {
                float4 wa = Wa[d], wb = Wb[d];
                if (wa.x + wb.x > 0.f) {
                    float4 p = __ldg(&g_tabT[(d << 5) + l]);
                    acc0.x += wa.x * p.x; acc0.y += wa.y * p.y; acc0.z += wa.z * p.z; acc0.w += wa.w * p.w;
                    acc1.x += wb.x * p.x; acc1.y += wb.y * p.y; acc1.z += wb.z * p.z; acc1.w += wb.w * p.w;
                    ss0.x += wa.x; ss0.y += wa.y; ss0.z += wa.z; ss0.w += wa.w;
                    ss1.x += wb.x; ss1.y += wb.y; ss1.z += wb.z; ss1.w += wb.w;
                }
            }

#pragma unroll
            for (int n = 0; n < 2; n++) {
                int t = base + 2 * w + n;
                if (t >= NN) break;
                float4 a  = (n == 0) ? acc0 : acc1;
                float4 ss = (n == 0) ? ss0  : ss1;
                float r0 = ss.x > 0.f ? 1.f / ss.x : 0.f;
                float r1 = ss.y > 0.f ? 1.f / ss.y : 0.f;
                float r2 = ss.z > 0.f ? 1.f / ss.z : 0.f;
                float r3 = ss.w > 0.f ? 1.f / ss.w : 0.f;
                float dg = (float)g_deg[t];
                float4 p = __ldg(&g_tabT[(__ldg(&nf[t]) << 5) + l]);

                float v0 = a.x * r0 + dg * p.x;
                float v1 = a.y * r1 + dg * p.y;
                float v2 = a.z * r2 + dg * p.z;
                float v3 = a.w * r3 + dg * p.w;

                float s = v0 + v1 + v2 + v3;
#pragma unroll
                for (int o = 16; o; o >>= 1) s += __shfl_xor_sync(0xFFFFFFFFu, s, o);
                float mu = s * (1.f / 128.f);
                float d0 = v0 - mu, d1 = v1 - mu, d2 = v2 - mu, d3 = v3 - mu;
                float sq = d0 * d0 + d1 * d1 + d2 * d2 + d3 * d3;
#pragma unroll
                for (int o = 16; o; o >>= 1) sq += __shfl_xor_sync(0xFFFFFFFFu, sq, o);
                float rs = rsqrtf(sq * (1.f / 128.f) + 1e-5f);

                float* o0 = out_node + (size_t)t * 128;
                __stcs(&o0[l],      d0 * rs * gl0 + bl0);
                __stcs(&o0[32 + l], d1 * rs * gl1 + bl1);
                __stcs(&o0[64 + l], d2 * rs * gl2 + bl2);
                __stcs(&o0[96 + l], d3 * rs * gl3 + bl3);
            }
        }
    }

    // ---- steal eout chunks [CHUNK_SPLIT, N_CHUNKS) ----
    for (;;) {
        if (tid == 0) s_chunk = atomicAdd(&g_ctrB, 1);
        __syncthreads();
        int c = CHUNK_SPLIT + s_chunk;
        __syncthreads();
        if (c >= N_CHUNKS) break;
        eout_chunk(ef, out_edge, c, tid);
    }
}

// ==================== launch ====================
extern "C" void kernel_launch(void* const* d_in, const int* in_sizes, int n_in,
                              void* d_out, int out_size) {
    const int*   nf       = (const int*)d_in[0];
    const int*   ef       = (const int*)d_in[1];
    const int*   ei       = (const int*)d_in[2];
    const float* node_emb = (const float*)d_in[3];
    const float* edge_emb = (const float*)d_in[4];
    const float* W_t      = (const float*)d_in[5];
    const float* b_t      = (const float*)d_in[6];
    const float* W_e      = (const float*)d_in[7];
    const float* b_e      = (const float*)d_in[8];
    const float* a_w      = (const float*)d_in[9];
    const float* a_b      = (const float*)d_in[10];
    const float* gamma    = (const float*)d_in[11];
    const float* beta     = (const float*)d_in[12];

    float* out_node = (float*)d_out;                                  // [25000,128]
    float4* out_edge = (float4*)((float*)d_out + (size_t)NN * 128);   // [400000,128]

    k1_init<<<K1_TOT, 256>>>(node_emb, edge_emb, W_t, b_t, W_e, b_e,
                             a_w, gamma, beta);
    k2_edges<<<KBLKS, 256>>>(nf, ef, ei, a_b, out_edge);
    k3_nodes<<<KBLKS, 256>>>(nf, ef, gamma, beta, out_node, out_edge);
}